// round 15
// baseline (speedup 1.0000x reference)
#include <cuda_runtime.h>
#include <cuda_bf16.h>
#include <cstdint>

// Modulated deformable conv: deformable-im2col + tf32 mma.sync GEMM.
// R15: BM=32 (784 tiles -> better wave packing: makespan 1.5T vs 2T),
// warp tile 16x64, B-fill one step ahead, prep kernels merged (ncu aligns
// onto the main kernel).
//   M = 25088 px, N = 256 cout, K = 2304. CTA: 32 px x 256 cout, TK=32.

#define CIN   256
#define COUT  256
#define HH    56
#define WW    56
#define NB    8
#define KTAPS 9
#define HWSZ  (HH*WW)
#define MTOT  (NB*HWSZ)        // 25088 = 784*32

#define BM 32
#define BN 256
#define TK 32
#define NT 256
#define NSTEP (KTAPS*CIN/TK)   // 72
#define NCHUNK (CIN/TK)        // 8

#define AP 36                  // As row stride (floats), conflict-free frag loads

#define SM_A      0
#define ABUF      (BM*AP*4)            // 4608
#define SM_B      (2*ABUF)             // 9216
#define BBUF      (TK*BN*4)            // 32768 (u64-packed)
#define SM_TOTAL  (SM_B + 2*BBUF)      // 74752

typedef unsigned int u32;
typedef unsigned long long u64;

__device__ float g_xn[NB * HH * WW * CIN];          // NHWC fp32
__device__ u32   g_wB[KTAPS * NCHUNK * TK * COUT];  // tf32, u64-pair swizzled tiles

// ---------------- helpers ----------------
__device__ __forceinline__ u32 cvt_tf32(float f) {
    u32 r;
    asm("cvt.rna.tf32.f32 %0, %1;" : "=r"(r) : "f"(f));
    return r;
}
__device__ __forceinline__ void cp_async16(void* smem_dst, const void* gmem_src) {
    u32 sa = (u32)__cvta_generic_to_shared(smem_dst);
    asm volatile("cp.async.ca.shared.global [%0], [%1], 16;" :: "r"(sa), "l"(gmem_src));
}
__device__ __forceinline__ void cp_commit() { asm volatile("cp.async.commit_group;" ::: "memory"); }
__device__ __forceinline__ void cp_wait1()  { asm volatile("cp.async.wait_group 1;" ::: "memory"); }
__device__ __forceinline__ void cp_wait0()  { asm volatile("cp.async.wait_group 0;" ::: "memory"); }

__device__ __forceinline__ void mma_tf32(float* d, const u32* a, u32 b0, u32 b1) {
    asm volatile(
        "mma.sync.aligned.m16n8k8.row.col.f32.tf32.tf32.f32 "
        "{%0,%1,%2,%3}, {%4,%5,%6,%7}, {%8,%9}, {%0,%1,%2,%3};"
        : "+f"(d[0]), "+f"(d[1]), "+f"(d[2]), "+f"(d[3])
        : "r"(a[0]), "r"(a[1]), "r"(a[2]), "r"(a[3]), "r"(b0), "r"(b1));
}

// ---------------- merged prep kernel ----------------
// blocks [0, WBLK): weight pack;  blocks [WBLK, WBLK+XBLK): x NCHW->NHWC
#define WBLK  (KTAPS*CIN*COUT/256)     // 2304
#define XBLK  (2*8*(NB*HH))            // 7168

__global__ void prep_kernel(const float* __restrict__ w, const float* __restrict__ x) {
    __shared__ float tile[32][33];
    int bid = blockIdx.x;
    int tx = threadIdx.x, ty = threadIdx.y;
    int tid = ty * 32 + tx;

    if (bid < WBLK) {
        int i = bid * 256 + tid;
        int k = i / (CIN * COUT);
        int r = i - k * (CIN * COUT);
        int o = r / CIN;
        int c = r - o * CIN;
        int chunk = c >> 5, cl = c & 31;
        int ks = cl >> 3, rem = cl & 7;
        int fc = rem & 3, half = rem >> 2;
        int i64 = o * 16 + ((ks * 4 + fc) ^ ((o & 3) << 2));
        g_wB[(k * NCHUNK + chunk) * (TK * COUT) + i64 * 2 + half] =
            cvt_tf32(w[(o * CIN + c) * KTAPS + k]);
        return;
    }
    int b = bid - WBLK;
    int wT = b & 1;
    int cT = (b >> 1) & 7;
    int nh = b >> 4;
    int n = nh / HH, h = nh - n * HH;
    #pragma unroll
    for (int i = 0; i < 4; ++i) {
        int c = cT * 32 + ty + i * 8;
        int ww = wT * 32 + tx;
        if (ww < WW)
            tile[ty + i * 8][tx] = x[((n * CIN + c) * HH + h) * WW + ww];
    }
    __syncthreads();
    #pragma unroll
    for (int i = 0; i < 4; ++i) {
        int ww = wT * 32 + ty + i * 8;
        int c = cT * 32 + tx;
        if (ww < WW)
            g_xn[((n * HH + h) * WW + ww) * CIN + c] = tile[tx][ty + i * 8];
    }
}

// ---------------- main kernel ----------------
__device__ __forceinline__ void calc_taps(int pg, int k,
                                          const float* __restrict__ offset,
                                          const float* __restrict__ mask,
                                          int* tb, float* tw) {
    int n = pg / HWSZ;
    int hw = pg - n * HWSZ;
    int h = hw / WW;
    int w = hw - h * WW;
    float dy = offset[((n * 18 + 2 * k    ) * HH + h) * WW + w];
    float dx = offset[((n * 18 + 2 * k + 1) * HH + h) * WW + w];
    float m  = mask  [((n * 9  + k        ) * HH + h) * WW + w];
    float py = dy + (float)(k / 3) + (float)(h - 1);
    float px = dx + (float)(k % 3) + (float)(w - 1);
    float y0f = floorf(py), x0f = floorf(px);
    float wy1 = py - y0f, wx1 = px - x0f;
    float wy0 = 1.0f - wy1, wx0 = 1.0f - wx1;
    int y0 = (int)y0f, x0 = (int)x0f;
    float w4[4] = { wy0 * wx0, wy0 * wx1, wy1 * wx0, wy1 * wx1 };
    #pragma unroll
    for (int t = 0; t < 4; ++t) {
        int yy = y0 + (t >> 1);
        int xx = x0 + (t & 1);
        bool valid = (yy >= 0) && (yy < HH) && (xx >= 0) && (xx < WW);
        int yc = min(max(yy, 0), HH - 1);
        int xc = min(max(xx, 0), WW - 1);
        tb[t] = ((n * HH + yc) * WW + xc) * CIN;
        tw[t] = valid ? w4[t] * m : 0.0f;
    }
}

__global__ __launch_bounds__(NT, 2) void mdcn_kernel(
    const float* __restrict__ offset,
    const float* __restrict__ mask,
    const float* __restrict__ bias,
    float* __restrict__ out)
{
    extern __shared__ char smem[];
    const int tid = threadIdx.x;
    const int wid = tid >> 5;
    const int lid = tid & 31;
    const int p0 = blockIdx.x * BM;

    const int wm = wid & 1;          // M warp (2 x 16 px)
    const int wn = wid >> 1;         // N warp (4 x 64 cout)
    const int fr = lid >> 2;         // frag row group 0..7
    const int fc = lid & 3;          // frag col group 0..3

    const int pA = tid >> 3;         // gather pixel 0..31
    const int cq = tid & 7;          // gather quad (4 cin) within 32

    int   tb[4];
    float tw[4];
    float4 rA[4];

    float acc[8][4];
    #pragma unroll
    for (int nt = 0; nt < 8; ++nt)
        #pragma unroll
        for (int j = 0; j < 4; ++j) acc[nt][j] = 0.0f;

    // ---- Prologue: taps + gather prefetch + B[0] issue ----
    calc_taps(p0 + pA, 0, offset, mask, tb, tw);
    {
        int c = cq * 4;
        #pragma unroll
        for (int t = 0; t < 4; ++t)
            rA[t] = *(const float4*)&g_xn[tb[t] + c];
    }
    {
        const char* src = (const char*)&g_wB[0];
        char* dstb = smem + SM_B;
        #pragma unroll
        for (int t = 0; t < 8; ++t) {
            int id = tid + t * NT;
            cp_async16(dstb + id * 16, src + id * 16);
        }
        cp_commit();
    }

    for (int step = 0; step < NSTEP; ++step) {
        const int buf = step & 1;

        // ---- combine prefetched corners -> tf32 -> As[buf] ----
        {
            char* abuf = smem + SM_A + buf * ABUF;
            float4 v0 = rA[0], v1 = rA[1], v2 = rA[2], v3 = rA[3];
            uint4 r;
            r.x = cvt_tf32(fmaf(tw[3], v3.x, fmaf(tw[2], v2.x, fmaf(tw[1], v1.x, tw[0] * v0.x))));
            r.y = cvt_tf32(fmaf(tw[3], v3.y, fmaf(tw[2], v2.y, fmaf(tw[1], v1.y, tw[0] * v0.y))));
            r.z = cvt_tf32(fmaf(tw[3], v3.z, fmaf(tw[2], v2.z, fmaf(tw[1], v1.z, tw[0] * v0.z))));
            r.w = cvt_tf32(fmaf(tw[3], v3.w, fmaf(tw[2], v2.w, fmaf(tw[1], v1.w, tw[0] * v0.w))));
            *(uint4*)(abuf + pA * (AP * 4) + cq * 16) = r;
        }

        if (step + 1 < NSTEP) {
            // ---- issue B[step+1] into the other buffer ----
            {
                const int k2 = (step + 1) >> 3;
                const int chunk2 = (step + 1) & 7;
                const char* src = (const char*)&g_wB[(k2 * NCHUNK + chunk2) * (TK * COUT)];
                char* dstb = smem + SM_B + (buf ^ 1) * BBUF;
                #pragma unroll
                for (int t = 0; t < 8; ++t) {
                    int id = tid + t * NT;
                    cp_async16(dstb + id * 16, src + id * 16);
                }
                cp_commit();
            }
            // ---- prefetch gather for step+1 ----
            if (((step + 1) & 7) == 0)
                calc_taps(p0 + pA, (step + 1) >> 3, offset, mask, tb, tw);
            int c = ((step + 1) & 7) * TK + cq * 4;
            #pragma unroll
            for (int t = 0; t < 4; ++t)
                rA[t] = *(const float4*)&g_xn[tb[t] + c];
            cp_wait1();          // B[step] complete (committed a full step ago)
        } else {
            cp_wait0();
        }
        __syncthreads();

        // ---- compute: 8 warps x (1 Mtile x 8 Ntiles) m16n8k8 tf32 ----
        {
            const u32* As = (const u32*)(smem + SM_A + buf * ABUF);
            const u64* Bs64 = (const u64*)(smem + SM_B + buf * BBUF);
            const int cbase = (wn * 64 + fr) * 16;
            #pragma unroll
            for (int ks = 0; ks < 4; ++ks) {
                int px = wm * 16 + fr;
                int ci = ks * 8 + fc;
                u32 a[4];
                a[0] = As[px * AP + ci];
                a[1] = As[(px + 8) * AP + ci];
                a[2] = As[px * AP + ci + 4];
                a[3] = As[(px + 8) * AP + ci + 4];
                const int C = (ks * 4 + fc) ^ ((fr & 3) << 2);
                #pragma unroll
                for (int nt = 0; nt < 8; ++nt) {
                    u64 b = Bs64[cbase + nt * 128 + C];
                    mma_tf32(acc[nt], a, (u32)b, (u32)(b >> 32));
                }
            }
        }
        __syncthreads();
    }

    // ---- Epilogue ----
    const int n  = p0 / HWSZ;              // CTA never straddles images (3136%32==0)
    const int hw0 = p0 - n * HWSZ;
    #pragma unroll
    for (int nt = 0; nt < 8; ++nt) {
        int o0 = wn * 64 + nt * 8 + fc * 2;
        float b0 = __ldg(&bias[o0]);
        float b1 = __ldg(&bias[o0 + 1]);
        int hwA = hw0 + wm * 16 + fr;
        long baseA = (long)(n * COUT + o0) * HWSZ + hwA;
        long baseB = baseA + 8;
        out[baseA]        = acc[nt][0] + b0;
        out[baseA + HWSZ] = acc[nt][1] + b1;
        out[baseB]        = acc[nt][2] + b0;
        out[baseB + HWSZ] = acc[nt][3] + b1;
    }
}

extern "C" void kernel_launch(void* const* d_in, const int* in_sizes, int n_in,
                              void* d_out, int out_size) {
    const float* x      = (const float*)d_in[0];
    const float* offset = (const float*)d_in[1];
    const float* mask   = (const float*)d_in[2];
    const float* weight = (const float*)d_in[3];
    const float* bias   = (const float*)d_in[4];
    float* out = (float*)d_out;

    cudaFuncSetAttribute(mdcn_kernel, cudaFuncAttributeMaxDynamicSharedMemorySize, SM_TOTAL);

    {
        dim3 block(32, 8);
        prep_kernel<<<WBLK + XBLK, block>>>(weight, x);
    }
    mdcn_kernel<<<MTOT / BM, NT, SM_TOTAL>>>(offset, mask, bias, out);
}

// round 16
// speedup vs baseline: 1.1827x; 1.1827x over previous
#include <cuda_runtime.h>
#include <cuda_fp16.h>
#include <cstdint>

// Modulated deformable conv: deformable-im2col + fp16 mma.sync (m16n8k16) GEMM.
// R16: BM=64 (best measured), all GEMM operands fp16 (same 11-bit mantissa as
// tf32 -> same accuracy), halving smem/L1 traffic and MMA instruction count.
//   M = 25088 px, N = 256 cout, K = 2304. CTA: 64 px x 256 cout, TK=32.

#define CIN   256
#define COUT  256
#define HH    56
#define WW    56
#define NB    8
#define KTAPS 9
#define HWSZ  (HH*WW)
#define MTOT  (NB*HWSZ)        // 25088 = 392*64

#define BM 64
#define BN 256
#define TK 32
#define NT 256
#define NSTEP (KTAPS*CIN/TK)   // 72
#define NCHUNK (CIN/TK)        // 8

#define APB 80                 // As row stride in BYTES (64B data + 16B pad)

#define SM_A      0
#define ABUF      (BM*APB)             // 5120
#define SM_B      (2*ABUF)             // 10240
#define BBUF      (TK*BN*2)            // 16384 (fp16, u64-packed)
#define SM_TOTAL  (SM_B + 2*BBUF)      // 43008

typedef unsigned int u32;
typedef unsigned long long u64;
typedef unsigned short u16;

__device__ float g_xn[NB * HH * WW * CIN];              // NHWC fp32
__device__ u16   g_wH[KTAPS * NCHUNK * 8 * COUT * 4];   // fp16 packed B tiles, 1.125MB

// ---------------- helpers ----------------
__device__ __forceinline__ u32 f2h2(float a, float b) {
    __half2 h = __floats2half2_rn(a, b);
    return *(u32*)&h;
}
__device__ __forceinline__ void cp_async16(void* smem_dst, const void* gmem_src) {
    u32 sa = (u32)__cvta_generic_to_shared(smem_dst);
    asm volatile("cp.async.ca.shared.global [%0], [%1], 16;" :: "r"(sa), "l"(gmem_src));
}
__device__ __forceinline__ void cp_commit() { asm volatile("cp.async.commit_group;" ::: "memory"); }
__device__ __forceinline__ void cp_wait1()  { asm volatile("cp.async.wait_group 1;" ::: "memory"); }
__device__ __forceinline__ void cp_wait0()  { asm volatile("cp.async.wait_group 0;" ::: "memory"); }

__device__ __forceinline__ void mma_f16(float* d, const u32* a, u32 b0, u32 b1) {
    asm volatile(
        "mma.sync.aligned.m16n8k16.row.col.f32.f16.f16.f32 "
        "{%0,%1,%2,%3}, {%4,%5,%6,%7}, {%8,%9}, {%0,%1,%2,%3};"
        : "+f"(d[0]), "+f"(d[1]), "+f"(d[2]), "+f"(d[3])
        : "r"(a[0]), "r"(a[1]), "r"(a[2]), "r"(a[3]), "r"(b0), "r"(b1));
}

// ---------------- merged prep kernel ----------------
// blocks [0, WBLK): weight fp16 pack;  [WBLK, WBLK+XBLK): x NCHW->NHWC
#define WBLK  (KTAPS*CIN*COUT/256)     // 2304
#define XBLK  (2*8*(NB*HH))            // 7168

__global__ void prep_kernel(const float* __restrict__ w, const float* __restrict__ x) {
    __shared__ float tile[32][33];
    int bid = blockIdx.x;
    int tx = threadIdx.x, ty = threadIdx.y;
    int tid = ty * 32 + tx;

    if (bid < WBLK) {
        int i = bid * 256 + tid;
        int k = i / (CIN * COUT);
        int r0 = i - k * (CIN * COUT);
        int o = r0 / CIN;
        int c = r0 - o * CIN;
        int chunk = c >> 5, kl = c & 31;
        int s = kl >> 4, r = kl & 15;
        int j  = ((r >> 3) & 1) * 2 + (r & 1);
        int fc = (r >> 1) & 3;
        int slot = o * 8 + ((s * 4 + fc) ^ ((o & 2) << 1));
        __half h = __float2half_rn(w[(o * CIN + c) * KTAPS + k]);
        g_wH[((k * NCHUNK + chunk) * (8 * COUT) + slot) * 4 + j] = *(u16*)&h;
        return;
    }
    int b = bid - WBLK;
    int wT = b & 1;
    int cT = (b >> 1) & 7;
    int nh = b >> 4;
    int n = nh / HH, h = nh - n * HH;
    #pragma unroll
    for (int i = 0; i < 4; ++i) {
        int c = cT * 32 + ty + i * 8;
        int ww = wT * 32 + tx;
        if (ww < WW)
            tile[ty + i * 8][tx] = x[((n * CIN + c) * HH + h) * WW + ww];
    }
    __syncthreads();
    #pragma unroll
    for (int i = 0; i < 4; ++i) {
        int ww = wT * 32 + ty + i * 8;
        int c = cT * 32 + tx;
        if (ww < WW)
            g_xn[((n * HH + h) * WW + ww) * CIN + c] = tile[tx][ty + i * 8];
    }
}

// ---------------- main kernel ----------------
__device__ __forceinline__ void calc_taps(int pg, int k,
                                          const float* __restrict__ offset,
                                          const float* __restrict__ mask,
                                          int* tb, float* tw) {
    int n = pg / HWSZ;
    int hw = pg - n * HWSZ;
    int h = hw / WW;
    int w = hw - h * WW;
    float dy = offset[((n * 18 + 2 * k    ) * HH + h) * WW + w];
    float dx = offset[((n * 18 + 2 * k + 1) * HH + h) * WW + w];
    float m  = mask  [((n * 9  + k        ) * HH + h) * WW + w];
    float py = dy + (float)(k / 3) + (float)(h - 1);
    float px = dx + (float)(k % 3) + (float)(w - 1);
    float y0f = floorf(py), x0f = floorf(px);
    float wy1 = py - y0f, wx1 = px - x0f;
    float wy0 = 1.0f - wy1, wx0 = 1.0f - wx1;
    int y0 = (int)y0f, x0 = (int)x0f;
    float w4[4] = { wy0 * wx0, wy0 * wx1, wy1 * wx0, wy1 * wx1 };
    #pragma unroll
    for (int t = 0; t < 4; ++t) {
        int yy = y0 + (t >> 1);
        int xx = x0 + (t & 1);
        bool valid = (yy >= 0) && (yy < HH) && (xx >= 0) && (xx < WW);
        int yc = min(max(yy, 0), HH - 1);
        int xc = min(max(xx, 0), WW - 1);
        tb[t] = ((n * HH + yc) * WW + xc) * CIN;
        tw[t] = valid ? w4[t] * m : 0.0f;
    }
}

__global__ __launch_bounds__(NT, 2) void mdcn_kernel(
    const float* __restrict__ offset,
    const float* __restrict__ mask,
    const float* __restrict__ bias,
    float* __restrict__ out)
{
    extern __shared__ char smem[];
    const int tid = threadIdx.x;
    const int wid = tid >> 5;
    const int lid = tid & 31;
    const int p0 = blockIdx.x * BM;

    const int wm = wid & 1;          // M warp (2 x 32 px)
    const int wn = wid >> 1;         // N warp (4 x 64 cout)
    const int fr = lid >> 2;         // frag row group 0..7
    const int fc = lid & 3;          // frag col group 0..3

    const int pA = tid >> 2;         // gather pixel 0..63
    const int cq = tid & 3;          // gather 8-cin group (contiguous)

    int   tb[4];
    float tw[4];
    float4 rA[2][4];                 // [half: cin +0/+4][corner]

    float acc[2][8][4];
    #pragma unroll
    for (int mt = 0; mt < 2; ++mt)
        #pragma unroll
        for (int nt = 0; nt < 8; ++nt)
            #pragma unroll
            for (int j = 0; j < 4; ++j) acc[mt][nt][j] = 0.0f;

    // ---- Prologue: taps + gather prefetch + B[0] issue ----
    calc_taps(p0 + pA, 0, offset, mask, tb, tw);
    #pragma unroll
    for (int half = 0; half < 2; ++half) {
        int c = cq * 8 + half * 4;
        #pragma unroll
        for (int t = 0; t < 4; ++t)
            rA[half][t] = *(const float4*)&g_xn[tb[t] + c];
    }
    {
        const char* src = (const char*)&g_wH[0];
        char* dstb = smem + SM_B;
        #pragma unroll
        for (int t = 0; t < 4; ++t) {
            int id = tid + t * NT;
            cp_async16(dstb + id * 16, src + id * 16);
        }
        cp_commit();
    }

    for (int step = 0; step < NSTEP; ++step) {
        const int buf = step & 1;

        // ---- combine prefetched corners -> fp16 -> As[buf] ----
        {
            char* abuf = smem + SM_A + buf * ABUF;
            uint4 r;
            u32 rr[2][2];
            #pragma unroll
            for (int half = 0; half < 2; ++half) {
                float4 v0 = rA[half][0], v1 = rA[half][1];
                float4 v2 = rA[half][2], v3 = rA[half][3];
                float fx = fmaf(tw[3], v3.x, fmaf(tw[2], v2.x, fmaf(tw[1], v1.x, tw[0] * v0.x)));
                float fy = fmaf(tw[3], v3.y, fmaf(tw[2], v2.y, fmaf(tw[1], v1.y, tw[0] * v0.y)));
                float fz = fmaf(tw[3], v3.z, fmaf(tw[2], v2.z, fmaf(tw[1], v1.z, tw[0] * v0.z)));
                float fw = fmaf(tw[3], v3.w, fmaf(tw[2], v2.w, fmaf(tw[1], v1.w, tw[0] * v0.w)));
                rr[half][0] = f2h2(fx, fy);
                rr[half][1] = f2h2(fz, fw);
            }
            r.x = rr[0][0]; r.y = rr[0][1]; r.z = rr[1][0]; r.w = rr[1][1];
            *(uint4*)(abuf + pA * APB + cq * 16) = r;
        }

        if (step + 1 < NSTEP) {
            // ---- issue B[step+1] into the other buffer ----
            {
                const int k2 = (step + 1) >> 3;
                const int chunk2 = (step + 1) & 7;
                const char* src = (const char*)&g_wH[(k2 * NCHUNK + chunk2) * (8 * COUT * 4)];
                char* dstb = smem + SM_B + (buf ^ 1) * BBUF;
                #pragma unroll
                for (int t = 0; t < 4; ++t) {
                    int id = tid + t * NT;
                    cp_async16(dstb + id * 16, src + id * 16);
                }
                cp_commit();
            }
            // ---- prefetch gather for step+1 (overlaps wait + MMA) ----
            if (((step + 1) & 7) == 0)
                calc_taps(p0 + pA, (step + 1) >> 3, offset, mask, tb, tw);
            int c0n = ((step + 1) & 7) * TK;
            #pragma unroll
            for (int half = 0; half < 2; ++half) {
                int c = c0n + cq * 8 + half * 4;
                #pragma unroll
                for (int t = 0; t < 4; ++t)
                    rA[half][t] = *(const float4*)&g_xn[tb[t] + c];
            }
            cp_wait1();          // B[step] complete (committed a full step ago)
        } else {
            cp_wait0();
        }
        __syncthreads();

        // ---- compute: 8 warps x (2 Mtiles x 8 Ntiles) m16n8k16 fp16 ----
        {
            const u32* As = (const u32*)(smem + SM_A + buf * ABUF);   // row stride 20 u32
            const u64* Bs64 = (const u64*)(smem + SM_B + buf * BBUF);
            const int cbase = (wn * 64 + fr) * 8;
            #pragma unroll
            for (int s = 0; s < 2; ++s) {
                u32 a[2][4];
                #pragma unroll
                for (int mt = 0; mt < 2; ++mt) {
                    int px = wm * 32 + mt * 16 + fr;
                    int ci = s * 8 + fc;
                    a[mt][0] = As[px * 20 + ci];
                    a[mt][1] = As[(px + 8) * 20 + ci];
                    a[mt][2] = As[px * 20 + ci + 4];
                    a[mt][3] = As[(px + 8) * 20 + ci + 4];
                }
                const int C = (s * 4 + fc) ^ ((fr & 2) << 1);
                #pragma unroll
                for (int nt = 0; nt < 8; ++nt) {
                    u64 b = Bs64[cbase + nt * 64 + C];
                    u32 b0 = (u32)b, b1 = (u32)(b >> 32);
                    mma_f16(acc[0][nt], a[0], b0, b1);
                    mma_f16(acc[1][nt], a[1], b0, b1);
                }
            }
        }
        __syncthreads();
    }

    // ---- Epilogue ----
    const int n  = p0 / HWSZ;              // CTA never straddles images (3136%64==0)
    const int hw0 = p0 - n * HWSZ;
    #pragma unroll
    for (int nt = 0; nt < 8; ++nt) {
        int o0 = wn * 64 + nt * 8 + fc * 2;
        float b0 = __ldg(&bias[o0]);
        float b1 = __ldg(&bias[o0 + 1]);
        #pragma unroll
        for (int mt = 0; mt < 2; ++mt) {
            int hwA = hw0 + wm * 32 + mt * 16 + fr;
            long baseA = (long)(n * COUT + o0) * HWSZ + hwA;
            long baseB = baseA + 8;
            out[baseA]        = acc[mt][nt][0] + b0;
            out[baseA + HWSZ] = acc[mt][nt][1] + b1;
            out[baseB]        = acc[mt][nt][2] + b0;
            out[baseB + HWSZ] = acc[mt][nt][3] + b1;
        }
    }
}

extern "C" void kernel_launch(void* const* d_in, const int* in_sizes, int n_in,
                              void* d_out, int out_size) {
    const float* x      = (const float*)d_in[0];
    const float* offset = (const float*)d_in[1];
    const float* mask   = (const float*)d_in[2];
    const float* weight = (const float*)d_in[3];
    const float* bias   = (const float*)d_in[4];
    float* out = (float*)d_out;

    cudaFuncSetAttribute(mdcn_kernel, cudaFuncAttributeMaxDynamicSharedMemorySize, SM_TOTAL);

    {
        dim3 block(32, 8);
        prep_kernel<<<WBLK + XBLK, block>>>(weight, x);
    }
    mdcn_kernel<<<MTOT / BM, NT, SM_TOTAL>>>(offset, mask, bias, out);
}